// round 1
// baseline (speedup 1.0000x reference)
#include <cuda_runtime.h>

// ---------------------------------------------------------------------------
// GatingNeuralAdaptiveBias: fused per-pixel dual-channel MLP + gate + LN.
// B=8, N=256 -> 524288 pixels. Thread-per-pixel, CTA = one (b,i) row (256 px).
// fp32 throughout, packed f32x2 FFMA2 in all GEMM inner loops.
// ---------------------------------------------------------------------------

typedef unsigned long long ull;

#define NTHREADS 256
#define NGRID    2048            // 8*256 rows

// shared memory layout (in floats)
#define OFF_W1   0               // 9*64   = 576
#define OFF_W2   576             // 64*64  = 4096
#define OFF_WG1  4672            // 128*64 = 8192
#define OFF_B1   12864           // 64
#define OFF_B2   12928           // 64
#define OFF_BG1  12992           // 64
#define OFF_WG2  13056           // 128  (64x2 interleaved)
#define OFF_BG2  13184           // 2 (+2 pad)
#define OFF_FG   13188           // 2*64
#define OFF_FB   13316           // 2*64
#define OFF_C1   13444           // 64 : ln_gamma[k]*Wo[k]
#define OFF_SBW  13508           // 1 (+3 pad): sum(ln_beta*Wo)+bo
#define OFF_E0   13512           // 64*256 transposed: E0[k*256 + p]
#define OFF_E1   29896           // 64*256
#define SMEM_FLOATS 46280
#define SMEM_BYTES  (SMEM_FLOATS * 4)   // 185120 B

__device__ __forceinline__ ull pack2(float lo, float hi) {
    ull r;
    asm("mov.b64 %0, {%1, %2};" : "=l"(r) : "f"(lo), "f"(hi));
    return r;
}
__device__ __forceinline__ void unpack2(ull v, float& lo, float& hi) {
    asm("mov.b64 {%0, %1}, %2;" : "=f"(lo), "=f"(hi) : "l"(v));
}
__device__ __forceinline__ void ffma2(ull& d, ull a, ull b) {
    asm("fma.rn.f32x2 %0, %1, %2, %0;" : "+l"(d) : "l"(a), "l"(b));
}
__device__ __forceinline__ float silu_f(float v) {
    return __fdividef(v, 1.0f + __expf(-v));
}

__global__ void __launch_bounds__(NTHREADS, 1)
gnab_kernel(const float* __restrict__ coords,
            const float* __restrict__ cost,
            const float* __restrict__ log_scale,
            const float* __restrict__ W1,  const float* __restrict__ b1,
            const float* __restrict__ W2,  const float* __restrict__ b2,
            const float* __restrict__ fg,  const float* __restrict__ fb,
            const float* __restrict__ Wg1, const float* __restrict__ bg1,
            const float* __restrict__ Wg2, const float* __restrict__ bg2,
            const float* __restrict__ temp,
            const float* __restrict__ lng, const float* __restrict__ lnb,
            const float* __restrict__ Wo,  const float* __restrict__ bo,
            float* __restrict__ out)
{
    extern __shared__ float sm[];
    const int tid = threadIdx.x;

    // ---- cooperative weight staging ----
    for (int t = tid; t < 576;  t += NTHREADS) sm[OFF_W1  + t] = W1[t];
    for (int t = tid; t < 4096; t += NTHREADS) sm[OFF_W2  + t] = W2[t];
    for (int t = tid; t < 8192; t += NTHREADS) sm[OFF_WG1 + t] = Wg1[t];
    if (tid < 64) {
        sm[OFF_B1  + tid] = b1[tid];
        sm[OFF_B2  + tid] = b2[tid];
        sm[OFF_BG1 + tid] = bg1[tid];
        sm[OFF_C1  + tid] = lng[tid] * Wo[tid];
    }
    if (tid < 128) {
        sm[OFF_WG2 + tid] = Wg2[tid];
        sm[OFF_FG  + tid] = fg[tid];
        sm[OFF_FB  + tid] = fb[tid];
    }
    if (tid < 2) sm[OFF_BG2 + tid] = bg2[tid];
    if (tid == 0) {
        float s = bo[0];
        for (int k = 0; k < 64; k++) s += lnb[k] * Wo[k];
        sm[OFF_SBW] = s;
    }
    __syncthreads();

    // ---- per-pixel scalars ----
    const int bi    = blockIdx.x;        // b*256 + i
    const int b     = bi >> 8;
    const int i     = bi & 255;
    const int j     = tid;               // column / pixel within row
    const int pixel = bi * 256 + j;

    const float cx = cost[pixel];
    const float dx = coords[(b * 256 + i) * 2 + 0] - coords[(b * 256 + j) * 2 + 0];
    const float dy = coords[(b * 256 + i) * 2 + 1] - coords[(b * 256 + j) * 2 + 1];
    const float ax = atan2f(dy, dx);

    float xv[2];  xv[0] = cx;  xv[1] = ax;
    float scl[2];
    scl[0] = __expf(log_scale[0]);
    scl[1] = __expf(log_scale[1]);
    const float itemp = __expf(-temp[0]);

    // =================== per-channel encoder ===================
    #pragma unroll 1
    for (int ch = 0; ch < 2; ++ch) {
        const float x  = xv[ch];
        const float sc = scl[ch];

        // Fourier features: [x, sin(fx), cos(fx) for f in 1,2,4,8] * exp(log_scale)
        float ft[9];
        ft[0] = x * sc;
        #pragma unroll
        for (int q = 0; q < 4; q++) {
            float s, c;
            sincosf(x * (float)(1 << q), &s, &c);
            ft[1 + 2 * q] = s * sc;
            ft[2 + 2 * q] = c * sc;
        }

        // ---- GEMM1: (9)->(64), packed ----
        ull acc[32];
        {
            const ull* bp = reinterpret_cast<const ull*>(&sm[OFF_B1]);
            #pragma unroll
            for (int m = 0; m < 32; m++) acc[m] = bp[m];
        }
        #pragma unroll
        for (int f = 0; f < 9; f++) {
            const ull fv = pack2(ft[f], ft[f]);
            const ulonglong2* Wv = reinterpret_cast<const ulonglong2*>(&sm[OFF_W1 + f * 64]);
            #pragma unroll
            for (int m = 0; m < 16; m++) {
                ulonglong2 w = Wv[m];
                ffma2(acc[2 * m],     fv, w.x);
                ffma2(acc[2 * m + 1], fv, w.y);
            }
        }
        float h1[64];
        #pragma unroll
        for (int m = 0; m < 32; m++) {
            float v0, v1;
            unpack2(acc[m], v0, v1);
            h1[2 * m]     = silu_f(v0);
            h1[2 * m + 1] = silu_f(v1);
        }

        // ---- GEMM2: (64)->(64), packed, h1 register-resident ----
        {
            const ull* bp = reinterpret_cast<const ull*>(&sm[OFF_B2]);
            #pragma unroll
            for (int m = 0; m < 32; m++) acc[m] = bp[m];
        }
        #pragma unroll
        for (int jj = 0; jj < 64; jj++) {
            const ull hh = pack2(h1[jj], h1[jj]);
            const ulonglong2* Wv = reinterpret_cast<const ulonglong2*>(&sm[OFF_W2 + jj * 64]);
            #pragma unroll
            for (int m = 0; m < 16; m++) {
                ulonglong2 w = Wv[m];
                ffma2(acc[2 * m],     hh, w.x);
                ffma2(acc[2 * m + 1], hh, w.y);
            }
        }

        // ---- FiLM + transposed store (conflict-free: lanes are consecutive p) ----
        float* Et = &sm[(ch == 0) ? OFF_E0 : OFF_E1];
        const float* g  = &sm[OFF_FG + ch * 64];
        const float* be = &sm[OFF_FB + ch * 64];
        #pragma unroll
        for (int m = 0; m < 32; m++) {
            float v0, v1;
            unpack2(acc[m], v0, v1);
            const int k0 = 2 * m;
            Et[k0 * 256 + j]       = v0 * g[k0]     + be[k0];
            Et[(k0 + 1) * 256 + j] = v1 * g[k0 + 1] + be[k0 + 1];
        }
    }
    // E rows are thread-private (same p written & read) -> no barrier needed.

    const float* E0 = &sm[OFF_E0];
    const float* E1 = &sm[OFF_E1];

    // =================== gate MLP: (128)->(64)->(2) ===================
    ull gacc[32];
    {
        const ull* bp = reinterpret_cast<const ull*>(&sm[OFF_BG1]);
        #pragma unroll
        for (int m = 0; m < 32; m++) gacc[m] = bp[m];
    }
    #pragma unroll 4
    for (int jj = 0; jj < 64; jj++) {
        const float gv = E0[jj * 256 + j];
        const ull gg = pack2(gv, gv);
        const ulonglong2* Wv = reinterpret_cast<const ulonglong2*>(&sm[OFF_WG1 + jj * 64]);
        #pragma unroll
        for (int m = 0; m < 16; m++) {
            ulonglong2 w = Wv[m];
            ffma2(gacc[2 * m],     gg, w.x);
            ffma2(gacc[2 * m + 1], gg, w.y);
        }
    }
    #pragma unroll 4
    for (int jj = 0; jj < 64; jj++) {
        const float gv = E1[jj * 256 + j];
        const ull gg = pack2(gv, gv);
        const ulonglong2* Wv = reinterpret_cast<const ulonglong2*>(&sm[OFF_WG1 + (64 + jj) * 64]);
        #pragma unroll
        for (int m = 0; m < 16; m++) {
            ulonglong2 w = Wv[m];
            ffma2(gacc[2 * m],     gg, w.x);
            ffma2(gacc[2 * m + 1], gg, w.y);
        }
    }
    float l0 = sm[OFF_BG2];
    float l1 = sm[OFF_BG2 + 1];
    #pragma unroll
    for (int m = 0; m < 32; m++) {
        float v0, v1;
        unpack2(gacc[m], v0, v1);
        v0 = silu_f(v0);
        v1 = silu_f(v1);
        const int k0 = 2 * m;
        l0 += v0 * sm[OFF_WG2 + 2 * k0]     + v1 * sm[OFF_WG2 + 2 * k0 + 2];
        l1 += v0 * sm[OFF_WG2 + 2 * k0 + 1] + v1 * sm[OFF_WG2 + 2 * k0 + 3];
    }
    // softmax over 2 logits / exp(temperature)  ==  sigmoid((l0-l1)*exp(-t))
    const float dlt = (l0 - l1) * itemp;
    const float w0  = __fdividef(1.0f, 1.0f + __expf(-dlt));
    const float w1  = 1.0f - w0;

    // =================== fuse + LayerNorm + output dot ===================
    float sum = 0.0f;
    #pragma unroll 8
    for (int k = 0; k < 64; k++)
        sum += w0 * E0[k * 256 + j] + w1 * E1[k * 256 + j];
    const float mu = sum * (1.0f / 64.0f);

    float var = 0.0f, dot = 0.0f;
    #pragma unroll 8
    for (int k = 0; k < 64; k++) {
        const float f = w0 * E0[k * 256 + j] + w1 * E1[k * 256 + j] - mu;
        var += f * f;
        dot += f * sm[OFF_C1 + k];
    }
    const float rstd = rsqrtf(var * (1.0f / 64.0f) + 1e-5f);

    out[pixel] = dot * rstd + sm[OFF_SBW];
}

extern "C" void kernel_launch(void* const* d_in, const int* in_sizes, int n_in,
                              void* d_out, int out_size)
{
    const float* coords = (const float*)d_in[0];
    const float* cost   = (const float*)d_in[1];
    const float* lsc    = (const float*)d_in[2];
    const float* W1     = (const float*)d_in[3];
    const float* b1     = (const float*)d_in[4];
    const float* W2     = (const float*)d_in[5];
    const float* b2     = (const float*)d_in[6];
    const float* fg     = (const float*)d_in[7];
    const float* fb     = (const float*)d_in[8];
    const float* Wg1    = (const float*)d_in[9];
    const float* bg1    = (const float*)d_in[10];
    const float* Wg2    = (const float*)d_in[11];
    const float* bg2    = (const float*)d_in[12];
    const float* temp   = (const float*)d_in[13];
    const float* lng    = (const float*)d_in[14];
    const float* lnb    = (const float*)d_in[15];
    const float* Wo     = (const float*)d_in[16];
    const float* bo     = (const float*)d_in[17];
    float* out          = (float*)d_out;

    cudaFuncSetAttribute(gnab_kernel,
                         cudaFuncAttributeMaxDynamicSharedMemorySize,
                         SMEM_BYTES);

    gnab_kernel<<<NGRID, NTHREADS, SMEM_BYTES>>>(
        coords, cost, lsc, W1, b1, W2, b2, fg, fb,
        Wg1, bg1, Wg2, bg2, temp, lng, lnb, Wo, bo, out);
}